// round 14
// baseline (speedup 1.0000x reference)
#include <cuda_runtime.h>
#include <cuda_fp16.h>
#include <cstdint>

// Conv2d 3x3 s1 p1: x(16,64,112,112) fp32, w(64,64,3,3), b(64) -> out(16,64,112,112)
//
// R14: R13 (fp16 m16n8k16, warp tile M=112 x N=32, 1008 MMA/warp balanced)
// with a 3-stage cp.async pipeline: wait_group 1 (fill is 2 chunks ahead,
// never exposed), single __syncthreads per chunk, double-MLP startup fill.

#define CIN  64
#define COUT 64
#define HH   112
#define WW   112
#define NB   16
#define HW   (HH*WW)

typedef unsigned long long ull;

#define XP      116                    // u pitch
#define XS_W64  (4 * 4 * XP)           // 1856 w64 (4 rows x 4 kv x XP u)
#define WS_W64  (9 * 4 * 68)           // 2448 w64
#define BUF_W64 (XS_W64 + WS_W64)      // 4304
#define BUF_BYTES (BUF_W64 * 8)        // 34432
#define SMEM_BYTES (3 * BUF_BYTES)     // 103296 (x2 CTA = 206.6KB/SM, fits)

// baked input: [n][ch4][row114][kv4][u XP] w64
__device__ ull g_x64[(size_t)NB * 4 * 114 * 4 * XP];
// baked weights: [ch4][kk9][kv4][68] w64
__device__ ull g_w64[4 * WS_W64];

#define PREP_X_THREADS ((size_t)NB * 4 * 114 * XP)
#define PREP_X_BLOCKS  ((unsigned)((PREP_X_THREADS + 255) / 256))
#define PREP_W_THREADS (4 * WS_W64)
#define PREP_W_BLOCKS  ((PREP_W_THREADS + 255) / 256)

__device__ __forceinline__ ull pack4(float a, float b, float c, float d) {
    __half2 lo = __floats2half2_rn(a, b);
    __half2 hi = __floats2half2_rn(c, d);
    return (ull)*(uint32_t*)&lo | ((ull)*(uint32_t*)&hi << 32);
}

__global__ void prep_all(const float* __restrict__ x,
                         const float* __restrict__ wt) {
    if (blockIdx.x >= PREP_X_BLOCKS) {
        int idx = (blockIdx.x - PREP_X_BLOCKS) * blockDim.x + threadIdx.x;
        if (idx >= PREP_W_THREADS) return;
        int f  = idx % 68;
        int t  = idx / 68;
        int kv = t & 3;
        int t2 = t >> 2;
        int kk = t2 % 9;
        int ch = t2 / 9;
        ull w = 0;
        if (f < 64) {
            int c0 = ch * 16 + 2 * kv;
            w = pack4(wt[(f * CIN + c0) * 9 + kk],
                      wt[(f * CIN + c0 + 1) * 9 + kk],
                      wt[(f * CIN + c0 + 8) * 9 + kk],
                      wt[(f * CIN + c0 + 9) * 9 + kk]);
        }
        g_w64[((ch * 9 + kk) * 4 + kv) * 68 + f] = w;
        return;
    }
    size_t idx = (size_t)blockIdx.x * blockDim.x + threadIdx.x;
    if (idx >= PREP_X_THREADS) return;
    int u    = idx % XP;                 // fastest -> coalesced x reads
    size_t t = idx / XP;
    int row  = t % 114;
    size_t t2 = t / 114;
    int ch   = t2 & 3;
    int n    = t2 >> 2;

    int gh = row - 1, gw = u - 1;
    bool ok = ((unsigned)gh < HH) && ((unsigned)gw < WW);
    const float* base = x + ((size_t)(n * CIN + ch * 16) * HH + gh) * WW + gw;
    ull* dst = g_x64 + (((size_t)(n * 4 + ch) * 114 + row) * 4) * XP + u;
    #pragma unroll
    for (int kv = 0; kv < 4; ++kv) {
        ull w = 0;
        if (ok) {
            const float* p = base + (size_t)(2 * kv) * HW;
            w = pack4(p[0], p[HW], p[8 * HW], p[9 * HW]);
        }
        dst[kv * XP] = w;
    }
}

#define MMA16(d, a0, a1, a2, a3, b0, b1)                                     \
    asm volatile("mma.sync.aligned.m16n8k16.row.col.f32.f16.f16.f32 "        \
        "{%0,%1,%2,%3}, {%4,%5,%6,%7}, {%8,%9}, {%0,%1,%2,%3};"              \
        : "+f"(d[0]), "+f"(d[1]), "+f"(d[2]), "+f"(d[3])                     \
        : "r"(a0), "r"(a1), "r"(a2), "r"(a3), "r"(b0), "r"(b1))

__device__ __forceinline__ void cp16(uint32_t dst, const void* src) {
    asm volatile("cp.async.ca.shared.global [%0], [%1], 16;"
                 :: "r"(dst), "l"(src));
}

__global__ __launch_bounds__(128, 2)
void conv_mma_kernel(const float* __restrict__ bias,
                     float* __restrict__ out) {
    extern __shared__ __align__(16) ull sm64[];
    const uint32_t sbase = (uint32_t)__cvta_generic_to_shared(sm64);

    const int tid  = threadIdx.x;
    const int lane = tid & 31;
    const int wid  = tid >> 5;            // 0..3
    const int qv   = lane >> 2;
    const int kv   = lane & 3;
    const int hpr  = wid >> 1;            // 0..1 : output row within pair
    const int nh   = wid & 1;             // 0..1 : N-half (f 0..31 / 32..63)

    const int n  = blockIdx.x / 56;
    const int h0 = (blockIdx.x % 56) * 2;

    float acc[7][4][4];
    #pragma unroll
    for (int t = 0; t < 7; ++t)
        #pragma unroll
        for (int j = 0; j < 4; ++j)
            #pragma unroll
            for (int r = 0; r < 4; ++r) acc[t][j][r] = 0.f;

    auto fill = [&](int ch, int b) {
        const uint4* xsrc = (const uint4*)(g_x64 +
            (((size_t)(n * 4 + ch) * 114 + h0) * 4) * XP);
        const uint4* wsrc = (const uint4*)(g_w64 + ch * WS_W64);
        uint32_t xdst = sbase + b * BUF_BYTES;
        uint32_t wdst = xdst + XS_W64 * 8;
        #pragma unroll 2
        for (int i = tid; i < XS_W64 / 2; i += 128)
            cp16(xdst + i * 16, xsrc + i);
        #pragma unroll 2
        for (int i = tid; i < WS_W64 / 2; i += 128)
            cp16(wdst + i * 16, wsrc + i);
        asm volatile("cp.async.commit_group;");
    };

    fill(0, 0);
    fill(1, 1);

    // per-warp lane bases (fragment offsets are compile-time immediates)
    const int albase = hpr * (4 * XP) + kv * XP + qv;
    const int wlbase = kv * 68 + nh * 32 + qv;

    #pragma unroll 1
    for (int ch = 0; ch < 4; ++ch) {
        const int b = (ch < 3) ? ch : 0;      // buffers 0,1,2,0
        if (ch < 3)
            asm volatile("cp.async.wait_group 1;");
        else
            asm volatile("cp.async.wait_group 0;");
        __syncthreads();
        if (ch < 2) fill(ch + 2, (ch == 0) ? 2 : 0);

        const ull* pa = sm64 + b * BUF_W64 + albase;
        const ull* pb = sm64 + b * BUF_W64 + XS_W64 + wlbase;

        #pragma unroll
        for (int kh = 0; kh < 3; ++kh) {
            #pragma unroll
            for (int kw = 0; kw < 3; ++kw) {
                const int kk = kh * 3 + kw;
                uint32_t A[7][4];
                #pragma unroll
                for (int t = 0; t < 7; ++t) {
                    ull va = pa[kh * (4 * XP) + 16 * t + kw];
                    ull vb = pa[kh * (4 * XP) + 16 * t + kw + 8];
                    A[t][0] = (uint32_t)va;
                    A[t][2] = (uint32_t)(va >> 32);
                    A[t][1] = (uint32_t)vb;
                    A[t][3] = (uint32_t)(vb >> 32);
                }
                #pragma unroll
                for (int j = 0; j < 4; ++j) {
                    ull bv = pb[kk * 272 + j * 8];
                    uint32_t b0 = (uint32_t)bv;
                    uint32_t b1 = (uint32_t)(bv >> 32);
                    #pragma unroll
                    for (int t = 0; t < 7; ++t)
                        MMA16(acc[t][j], A[t][0], A[t][1], A[t][2], A[t][3], b0, b1);
                }
            }
        }
        // no trailing barrier: with 3 buffers, the next overwrite of buffer b
        // happens >= 2 iterations later, behind that iteration's top barrier.
    }

    // ---- direct epilogue: fragments + bias -> global (no guards needed) ----
    float bj0[4], bj1[4];
    #pragma unroll
    for (int j = 0; j < 4; ++j) {
        bj0[j] = __ldg(bias + nh * 32 + j * 8 + kv * 2);
        bj1[j] = __ldg(bias + nh * 32 + j * 8 + kv * 2 + 1);
    }
    const int hh = h0 + hpr;
    #pragma unroll
    for (int t = 0; t < 7; ++t) {
        const int ub = 16 * t + qv;
        #pragma unroll
        for (int j = 0; j < 4; ++j) {
            const int f0 = nh * 32 + j * 8 + kv * 2;
            float* o0 = out + ((size_t)(n * COUT + f0) * HH + hh) * WW;
            o0[ub]          = acc[t][j][0] + bj0[j];
            o0[HW + ub]     = acc[t][j][1] + bj1[j];
            o0[ub + 8]      = acc[t][j][2] + bj0[j];
            o0[HW + ub + 8] = acc[t][j][3] + bj1[j];
        }
    }
}

extern "C" void kernel_launch(void* const* d_in, const int* in_sizes, int n_in,
                              void* d_out, int out_size) {
    const float* x    = (const float*)d_in[0];
    const float* wt   = (const float*)d_in[1];
    const float* bias = (const float*)d_in[2];
    float* out = (float*)d_out;

    cudaFuncSetAttribute(conv_mma_kernel,
                         cudaFuncAttributeMaxDynamicSharedMemorySize, SMEM_BYTES);
    prep_all<<<PREP_X_BLOCKS + PREP_W_BLOCKS, 256>>>(x, wt);
    conv_mma_kernel<<<NB * 56, 128, SMEM_BYTES>>>(bias, out);
}

// round 15
// speedup vs baseline: 1.0930x; 1.0930x over previous
#include <cuda_runtime.h>
#include <cuda_fp16.h>
#include <cstdint>

// Conv2d 3x3 s1 p1: x(16,64,112,112) fp32, w(64,64,3,3), b(64) -> out(16,64,112,112)
//
// R15: R13 base (fp16 m16n8k16, warp tile M=112 x N=32, 2-buffer cp.async).
// Per-k-step body split into two M-halves (4+3 m16 tiles) so live regs drop
// to ~150 -> real 3 CTAs/SM (12 warps/SM, waves 3.03 -> 2.02).

#define CIN  64
#define COUT 64
#define HH   112
#define WW   112
#define NB   16
#define HW   (HH*WW)

typedef unsigned long long ull;

#define XP      116                    // u pitch
#define XS_W64  (4 * 4 * XP)           // 1856 w64 (4 rows x 4 kv x XP u)
#define WS_W64  (9 * 4 * 68)           // 2448 w64
#define BUF_W64 (XS_W64 + WS_W64)      // 4304
#define BUF_BYTES (BUF_W64 * 8)        // 34432
#define SMEM_BYTES (2 * BUF_BYTES)     // 68864 (x3 CTA = 206.6KB/SM, fits)

// baked input: [n][ch4][row114][kv4][u XP] w64
__device__ ull g_x64[(size_t)NB * 4 * 114 * 4 * XP];
// baked weights: [ch4][kk9][kv4][68] w64
__device__ ull g_w64[4 * WS_W64];

#define PREP_X_THREADS ((size_t)NB * 4 * 114 * XP)
#define PREP_X_BLOCKS  ((unsigned)((PREP_X_THREADS + 255) / 256))
#define PREP_W_THREADS (4 * WS_W64)
#define PREP_W_BLOCKS  ((PREP_W_THREADS + 255) / 256)

__device__ __forceinline__ ull pack4(float a, float b, float c, float d) {
    __half2 lo = __floats2half2_rn(a, b);
    __half2 hi = __floats2half2_rn(c, d);
    return (ull)*(uint32_t*)&lo | ((ull)*(uint32_t*)&hi << 32);
}

__global__ void prep_all(const float* __restrict__ x,
                         const float* __restrict__ wt) {
    if (blockIdx.x >= PREP_X_BLOCKS) {
        int idx = (blockIdx.x - PREP_X_BLOCKS) * blockDim.x + threadIdx.x;
        if (idx >= PREP_W_THREADS) return;
        int f  = idx % 68;
        int t  = idx / 68;
        int kv = t & 3;
        int t2 = t >> 2;
        int kk = t2 % 9;
        int ch = t2 / 9;
        ull w = 0;
        if (f < 64) {
            int c0 = ch * 16 + 2 * kv;
            w = pack4(wt[(f * CIN + c0) * 9 + kk],
                      wt[(f * CIN + c0 + 1) * 9 + kk],
                      wt[(f * CIN + c0 + 8) * 9 + kk],
                      wt[(f * CIN + c0 + 9) * 9 + kk]);
        }
        g_w64[((ch * 9 + kk) * 4 + kv) * 68 + f] = w;
        return;
    }
    size_t idx = (size_t)blockIdx.x * blockDim.x + threadIdx.x;
    if (idx >= PREP_X_THREADS) return;
    int u    = idx % XP;                 // fastest -> coalesced x reads
    size_t t = idx / XP;
    int row  = t % 114;
    size_t t2 = t / 114;
    int ch   = t2 & 3;
    int n    = t2 >> 2;

    int gh = row - 1, gw = u - 1;
    bool ok = ((unsigned)gh < HH) && ((unsigned)gw < WW);
    const float* base = x + ((size_t)(n * CIN + ch * 16) * HH + gh) * WW + gw;
    ull* dst = g_x64 + (((size_t)(n * 4 + ch) * 114 + row) * 4) * XP + u;
    #pragma unroll
    for (int kv = 0; kv < 4; ++kv) {
        ull w = 0;
        if (ok) {
            const float* p = base + (size_t)(2 * kv) * HW;
            w = pack4(p[0], p[HW], p[8 * HW], p[9 * HW]);
        }
        dst[kv * XP] = w;
    }
}

#define MMA16(d, a0, a1, a2, a3, b0, b1)                                     \
    asm volatile("mma.sync.aligned.m16n8k16.row.col.f32.f16.f16.f32 "        \
        "{%0,%1,%2,%3}, {%4,%5,%6,%7}, {%8,%9}, {%0,%1,%2,%3};"              \
        : "+f"(d[0]), "+f"(d[1]), "+f"(d[2]), "+f"(d[3])                     \
        : "r"(a0), "r"(a1), "r"(a2), "r"(a3), "r"(b0), "r"(b1))

__device__ __forceinline__ void cp16(uint32_t dst, const void* src) {
    asm volatile("cp.async.ca.shared.global [%0], [%1], 16;"
                 :: "r"(dst), "l"(src));
}

__global__ __launch_bounds__(128, 3)
void conv_mma_kernel(const float* __restrict__ bias,
                     float* __restrict__ out) {
    extern __shared__ __align__(16) ull sm64[];
    const uint32_t sbase = (uint32_t)__cvta_generic_to_shared(sm64);

    const int tid  = threadIdx.x;
    const int lane = tid & 31;
    const int wid  = tid >> 5;            // 0..3
    const int qv   = lane >> 2;
    const int kv   = lane & 3;
    const int hpr  = wid >> 1;            // 0..1 : output row within pair
    const int nh   = wid & 1;             // 0..1 : N-half (f 0..31 / 32..63)

    const int n  = blockIdx.x / 56;
    const int h0 = (blockIdx.x % 56) * 2;

    float acc[7][4][4];
    #pragma unroll
    for (int t = 0; t < 7; ++t)
        #pragma unroll
        for (int j = 0; j < 4; ++j)
            #pragma unroll
            for (int r = 0; r < 4; ++r) acc[t][j][r] = 0.f;

    auto fill = [&](int ch, int b) {
        const uint4* xsrc = (const uint4*)(g_x64 +
            (((size_t)(n * 4 + ch) * 114 + h0) * 4) * XP);
        const uint4* wsrc = (const uint4*)(g_w64 + ch * WS_W64);
        uint32_t xdst = sbase + b * BUF_BYTES;
        uint32_t wdst = xdst + XS_W64 * 8;
        #pragma unroll 2
        for (int i = tid; i < XS_W64 / 2; i += 128)
            cp16(xdst + i * 16, xsrc + i);
        #pragma unroll 2
        for (int i = tid; i < WS_W64 / 2; i += 128)
            cp16(wdst + i * 16, wsrc + i);
        asm volatile("cp.async.commit_group;");
    };

    fill(0, 0);

    // per-warp lane bases (fragment offsets are compile-time immediates)
    const int albase = hpr * (4 * XP) + kv * XP + qv;
    const int wlbase = kv * 68 + nh * 32 + qv;

    #pragma unroll 1
    for (int ch = 0; ch < 4; ++ch) {
        const int b = ch & 1;
        asm volatile("cp.async.wait_group 0;");
        __syncthreads();
        if (ch < 3) fill(ch + 1, b ^ 1);

        const ull* pa = sm64 + b * BUF_W64 + albase;
        const ull* pb = sm64 + b * BUF_W64 + XS_W64 + wlbase;

        #pragma unroll
        for (int kh = 0; kh < 3; ++kh) {
            #pragma unroll
            for (int kw = 0; kw < 3; ++kw) {
                const int kk = kh * 3 + kw;
                // B fragments once per k-step (8 regs, reused by both halves)
                uint32_t Bw[4][2];
                #pragma unroll
                for (int j = 0; j < 4; ++j) {
                    ull bv = pb[kk * 272 + j * 8];
                    Bw[j][0] = (uint32_t)bv;
                    Bw[j][1] = (uint32_t)(bv >> 32);
                }
                // two M-halves: t=0..3 then t=4..6 (live A regs 16 max)
                #pragma unroll
                for (int th = 0; th < 2; ++th) {
                    const int t0 = th * 4;
                    const int tn = th ? 3 : 4;
                    uint32_t A[4][4];
                    #pragma unroll
                    for (int t = 0; t < 4; ++t) {
                        if (t < tn) {
                            ull va = pa[kh * (4 * XP) + 16 * (t0 + t) + kw];
                            ull vb = pa[kh * (4 * XP) + 16 * (t0 + t) + kw + 8];
                            A[t][0] = (uint32_t)va;
                            A[t][2] = (uint32_t)(va >> 32);
                            A[t][1] = (uint32_t)vb;
                            A[t][3] = (uint32_t)(vb >> 32);
                        }
                    }
                    #pragma unroll
                    for (int j = 0; j < 4; ++j) {
                        #pragma unroll
                        for (int t = 0; t < 4; ++t) {
                            if (t < tn)
                                MMA16(acc[t0 + t][j], A[t][0], A[t][1],
                                      A[t][2], A[t][3], Bw[j][0], Bw[j][1]);
                        }
                    }
                }
            }
        }
        __syncthreads();   // all warps done with buffer b before refill (ch+2)
    }

    // ---- direct epilogue: fragments + bias -> global (no guards needed) ----
    float bj0[4], bj1[4];
    #pragma unroll
    for (int j = 0; j < 4; ++j) {
        bj0[j] = __ldg(bias + nh * 32 + j * 8 + kv * 2);
        bj1[j] = __ldg(bias + nh * 32 + j * 8 + kv * 2 + 1);
    }
    const int hh = h0 + hpr;
    #pragma unroll
    for (int t = 0; t < 7; ++t) {
        const int ub = 16 * t + qv;
        #pragma unroll
        for (int j = 0; j < 4; ++j) {
            const int f0 = nh * 32 + j * 8 + kv * 2;
            float* o0 = out + ((size_t)(n * COUT + f0) * HH + hh) * WW;
            o0[ub]          = acc[t][j][0] + bj0[j];
            o0[HW + ub]     = acc[t][j][1] + bj1[j];
            o0[ub + 8]      = acc[t][j][2] + bj0[j];
            o0[HW + ub + 8] = acc[t][j][3] + bj1[j];
        }
    }
}

extern "C" void kernel_launch(void* const* d_in, const int* in_sizes, int n_in,
                              void* d_out, int out_size) {
    const float* x    = (const float*)d_in[0];
    const float* wt   = (const float*)d_in[1];
    const float* bias = (const float*)d_in[2];
    float* out = (float*)d_out;

    cudaFuncSetAttribute(conv_mma_kernel,
                         cudaFuncAttributeMaxDynamicSharedMemorySize, SMEM_BYTES);
    prep_all<<<PREP_X_BLOCKS + PREP_W_BLOCKS, 256>>>(x, wt);
    conv_mma_kernel<<<NB * 56, 128, SMEM_BYTES>>>(bias, out);
}